// round 14
// baseline (speedup 1.0000x reference)
#include <cuda_runtime.h>
#include <cuda_bf16.h>
#include <cstdint>

// x: (128, 512, 14, 14) fp32 ; W: (20, 512) fp32
// T=8, n=16, B=3136, c=512, H=4, K=5, O=20
#define NT   128
#define CCH  512
#define HWS  196
#define TT   8
#define NN   16
#define HH   4
#define KK   5
#define OO   20
#define BB   3136   // NN * HWS

// scratch: softmax weights, layout [h][t][k][B]  (coalesced at both ends)
__device__ float g_weights[(size_t)HH * TT * KK * BB];
#define GW_IDX(h, t, k, b) ((((size_t)(h) * TT + (t)) * KK + (k)) * BB + (b))

// ---------------- kernel 1: TF32 tensor-core logits + softmax (R13 exact) ---
#define KC      32                    // channels per staged chunk
#define NCHUNK  16                    // 512 / 32
#define NBUF    2
#define APITCH  104                   // smem pitch (104%32==8 -> conflict-free)
#define ABUF    (KC * APITCH)         // 3328 floats per buffer
#define WTP     20                    // W^T pitch: Wt[k][n], n=0..19
#define SMEM1_BYTES ((NBUF * ABUF + CCH * WTP + 16) * 4)   // 67648 (16f guard)

__device__ __forceinline__ uint32_t smem_u32(const void* p) {
    uint32_t a;
    asm("{ .reg .u64 t; cvta.to.shared.u64 t, %1; cvt.u32.u64 %0, t; }"
        : "=r"(a) : "l"(p));
    return a;
}

#define MMA_TF32(d, a0, a1, a2, a3, b0, b1)                                   \
    asm volatile("mma.sync.aligned.m16n8k8.row.col.f32.tf32.tf32.f32 "        \
                 "{%0,%1,%2,%3}, {%4,%5,%6,%7}, {%8,%9}, {%0,%1,%2,%3};"      \
                 : "+f"(d[0]), "+f"(d[1]), "+f"(d[2]), "+f"(d[3])             \
                 : "r"(a0), "r"(a1), "r"(a2), "r"(a3), "r"(b0), "r"(b1))

#define CP16(daddr, saddr)                                                    \
    asm volatile("cp.async.cg.shared.global [%0], [%1], 16;"                  \
                 :: "r"(daddr), "l"((const void*)(saddr)) : "memory")

__global__ void __launch_bounds__(256)
weights_mma_kernel(const float* __restrict__ x, const float* __restrict__ W)
{
    extern __shared__ float smem[];
    float* Abuf = smem;                    // [2][KC][APITCH]
    float* Wt   = smem + NBUF * ABUF;      // [512][20] : Wt[k*20+n] = W[n][k]

    const int tid  = threadIdx.x;
    const int bid  = blockIdx.x;
    const int nt   = bid >> 1;             // image 0..127
    const int half = bid & 1;
    const int off  = half * 96;            // global sp offset of this half
    const int nsp  = half ? 100 : 96;
    const int ntiles = half ? 7 : 6;       // m16 tiles

    const int w  = tid >> 5;
    const int l  = tid & 31;
    const int lg = l >> 2;                 // 0..7
    const int lc = l & 3;                  // 0..3

    // stage W transposed (raw fp32; mma HW truncates to tf32)
    for (int i = tid; i < OO * CCH; i += 256) {
        const int n = i >> 9, k = i & (CCH - 1);
        Wt[k * WTP + n] = W[i];
    }

    const float* xbase = x + (size_t)nt * CCH * HWS + off;
    const uint32_t abase_u32 = smem_u32(Abuf);

    auto stage = [&](int ck) {
        const float* src = xbase + (size_t)ck * KC * HWS;
        const uint32_t dst0 = abase_u32 + (ck & (NBUF - 1)) * (ABUF * 4);
        if (half == 0) {
            for (int f = tid; f < KC * 24; f += 256) {
                const int c = f / 24, i = f - c * 24;
                CP16(dst0 + (c * APITCH + 4 * i) * 4, src + c * HWS + 4 * i);
            }
        } else {
            for (int f = tid; f < KC * 25; f += 256) {
                const int c = f / 25, i = f - c * 25;
                CP16(dst0 + (c * APITCH + 4 * i) * 4, src + c * HWS + 4 * i);
            }
        }
        asm volatile("cp.async.commit_group;" ::: "memory");
    };

    const bool tvalid = (w < ntiles);
    const int sp0 = 16 * w + lg;
    const int spa = min(sp0, APITCH - 1);
    const int spb = min(sp0 + 8, APITCH - 1);

    float d[3][4];
#pragma unroll
    for (int nf = 0; nf < 3; ++nf)
#pragma unroll
        for (int r = 0; r < 4; ++r) d[nf][r] = 0.f;

    stage(0); stage(1);

    for (int ck = 0; ck < NCHUNK; ++ck) {
        if (ck < NCHUNK - 1) {
            asm volatile("cp.async.wait_group 1;" ::: "memory");
        } else {
            asm volatile("cp.async.wait_group 0;" ::: "memory");
        }
        __syncthreads();

        const float* Ab = Abuf + (ck & (NBUF - 1)) * ABUF;
#pragma unroll
        for (int k8 = 0; k8 < KC / 8; ++k8) {
            const int kl = k8 * 8;
            const int kg = ck * KC + kl + lc;
            uint32_t bfr[3][2];
#pragma unroll
            for (int nf = 0; nf < 3; ++nf) {
                bfr[nf][0] = __float_as_uint(Wt[kg * WTP + 8 * nf + lg]);
                bfr[nf][1] = __float_as_uint(Wt[(kg + 4) * WTP + 8 * nf + lg]);
            }
            if (tvalid) {
                const float* r0 = Ab + (kl + lc) * APITCH;
                const float* r4 = Ab + (kl + lc + 4) * APITCH;
                const uint32_t a0 = __float_as_uint(r0[spa]);
                const uint32_t a1 = __float_as_uint(r0[spb]);
                const uint32_t a2 = __float_as_uint(r4[spa]);
                const uint32_t a3 = __float_as_uint(r4[spb]);
#pragma unroll
                for (int nf = 0; nf < 3; ++nf)
                    MMA_TF32(d[nf], a0, a1, a2, a3, bfr[nf][0], bfr[nf][1]);
            }
        }
        __syncthreads();
        if (ck + 2 < NCHUNK) stage(ck + 2);
    }

    // exchange D through smem (reuse Abuf region): Dx[112][24]
    float* Dx = smem;
    if (tvalid) {
        const int r = 16 * w + lg;
#pragma unroll
        for (int nf = 0; nf < 3; ++nf) {
            const int col = nf * 8 + 2 * lc;
            Dx[r * 24 + col]           = d[nf][0];
            Dx[r * 24 + col + 1]       = d[nf][1];
            Dx[(r + 8) * 24 + col]     = d[nf][2];
            Dx[(r + 8) * 24 + col + 1] = d[nf][3];
        }
    }
    __syncthreads();

    const int t_  = nt & (TT - 1);
    const int n_i = nt >> 3;
    for (int s = tid; s < nsp; s += 256) {
        const float* row = Dx + s * 24;
        const int b = n_i * HWS + off + s;
#pragma unroll
        for (int h = 0; h < HH; ++h) {
            float lo[KK];
#pragma unroll
            for (int k = 0; k < KK; ++k) lo[k] = row[h * KK + k];
            float m = lo[0];
#pragma unroll
            for (int k = 1; k < KK; ++k) m = fmaxf(m, lo[k]);
            float e[KK], sum = 0.f;
#pragma unroll
            for (int k = 0; k < KK; ++k) { e[k] = __expf(lo[k] - m); sum += e[k]; }
            const float inv = 1.f / sum;
#pragma unroll
            for (int k = 0; k < KK; ++k)
                g_weights[GW_IDX(h, t_, k, b)] = e[k] * inv;
        }
    }
}

// ---------------- kernel 2: causal 5-tap combine, float4-vectorized ---------
// grid = (n_i : 16, ct : 16) ; block = 196 threads = 49 f4-groups x 4 c-lanes.
// Each thread: 4 consecutive sp (float4) x 8 channels x 8 t = 256 outputs.
// All x/out accesses are LDG.128/STG.128; weights are float4 along B
// (L1-resident after first channel pair, broadcast across c-lanes).
__global__ void __launch_bounds__(196, 2)
combine_kernel(const float* __restrict__ x, float* __restrict__ out)
{
    const int n_i = blockIdx.x;
    const int ct  = blockIdx.y;           // 32-channel tile
    const int h   = ct >> 2;              // head

    const int tid = threadIdx.x;
    const int g   = tid % 49;             // float4 group (sp = 4g)
    const int cl  = tid / 49;             // channel lane 0..3
    const int b0  = n_i * HWS + 4 * g;
    const int cbase = ct * 32 + cl * 8;

    const size_t tstride = (size_t)CCH * HWS;
    const size_t base = (size_t)n_i * TT * CCH * HWS + (size_t)4 * g;

#pragma unroll
    for (int cp = 0; cp < 4; ++cp) {
        const int c0 = cbase + 2 * cp;
        const float* xp0 = x + base + (size_t)c0 * HWS;
        const float* xp1 = xp0 + HWS;

        float4 xv0[TT], xv1[TT];
#pragma unroll
        for (int t = 0; t < TT; ++t)
            xv0[t] = *reinterpret_cast<const float4*>(xp0 + (size_t)t * tstride);
#pragma unroll
        for (int t = 0; t < TT; ++t)
            xv1[t] = *reinterpret_cast<const float4*>(xp1 + (size_t)t * tstride);

        float* op0 = out + base + (size_t)c0 * HWS;
        float* op1 = op0 + HWS;

#pragma unroll
        for (int t = 0; t < TT; ++t) {
            float4 a0 = make_float4(0.f, 0.f, 0.f, 0.f);
            float4 a1 = make_float4(0.f, 0.f, 0.f, 0.f);
#pragma unroll
            for (int k = 0; k < KK; ++k) {
                const int src = t + k - 4;               // causal left pad
                if (src >= 0) {
                    const float4 w4 = *reinterpret_cast<const float4*>(
                        &g_weights[GW_IDX(h, t, k, b0)]);
                    a0.x = fmaf(w4.x, xv0[src].x, a0.x);
                    a0.y = fmaf(w4.y, xv0[src].y, a0.y);
                    a0.z = fmaf(w4.z, xv0[src].z, a0.z);
                    a0.w = fmaf(w4.w, xv0[src].w, a0.w);
                    a1.x = fmaf(w4.x, xv1[src].x, a1.x);
                    a1.y = fmaf(w4.y, xv1[src].y, a1.y);
                    a1.z = fmaf(w4.z, xv1[src].z, a1.z);
                    a1.w = fmaf(w4.w, xv1[src].w, a1.w);
                }
            }
            *reinterpret_cast<float4*>(op0 + (size_t)t * tstride) = a0;
            *reinterpret_cast<float4*>(op1 + (size_t)t * tstride) = a1;
        }
    }
}

// ---------------------------------------------------------------------------
extern "C" void kernel_launch(void* const* d_in, const int* in_sizes, int n_in,
                              void* d_out, int out_size)
{
    const float* x = (const float*)d_in[0];
    const float* W = (const float*)d_in[1];
    float* out = (float*)d_out;

    cudaFuncSetAttribute(weights_mma_kernel,
                         cudaFuncAttributeMaxDynamicSharedMemorySize, SMEM1_BYTES);

    weights_mma_kernel<<<2 * NT, 256, SMEM1_BYTES>>>(x, W);
    combine_kernel<<<dim3(NN, 16), 196>>>(x, out);
}

// round 15
// speedup vs baseline: 1.7338x; 1.7338x over previous
#include <cuda_runtime.h>
#include <cuda_bf16.h>
#include <cstdint>

// x: (128, 512, 14, 14) fp32 ; W: (20, 512) fp32
// T=8, n=16, B=3136, c=512, H=4, K=5, O=20
#define NT   128
#define CCH  512
#define HWS  196
#define TT   8
#define NN   16
#define HH   4
#define KK   5
#define OO   20
#define BB   3136   // NN * HWS

// scratch: softmax weights, layout [h][t][k][B]
__device__ float g_weights[(size_t)HH * TT * KK * BB];
#define GW_IDX(h, t, k, b) ((((size_t)(h) * TT + (t)) * KK + (k)) * BB + (b))

// per-segment sync counters (zero-init at load; self-reset each run)
__device__ unsigned g_arrive[NN];
__device__ unsigned g_done[NN];

// ---------------- fused kernel: phase1 = R13 K1, phase2 = R11 K2 ------------
#define KC      32
#define NCHUNK  16
#define NBUF    2
#define APITCH  104
#define ABUF    (KC * APITCH)
#define WTP     20
#define SMEM1_BYTES ((NBUF * ABUF + CCH * WTP + 16) * 4)   // 67648 -> 3 CTA/SM

__device__ __forceinline__ uint32_t smem_u32(const void* p) {
    uint32_t a;
    asm("{ .reg .u64 t; cvta.to.shared.u64 t, %1; cvt.u32.u64 %0, t; }"
        : "=r"(a) : "l"(p));
    return a;
}

#define MMA_TF32(d, a0, a1, a2, a3, b0, b1)                                   \
    asm volatile("mma.sync.aligned.m16n8k8.row.col.f32.tf32.tf32.f32 "        \
                 "{%0,%1,%2,%3}, {%4,%5,%6,%7}, {%8,%9}, {%0,%1,%2,%3};"      \
                 : "+f"(d[0]), "+f"(d[1]), "+f"(d[2]), "+f"(d[3])             \
                 : "r"(a0), "r"(a1), "r"(a2), "r"(a3), "r"(b0), "r"(b1))

#define CP16(daddr, saddr)                                                    \
    asm volatile("cp.async.cg.shared.global [%0], [%1], 16;"                  \
                 :: "r"(daddr), "l"((const void*)(saddr)) : "memory")

__global__ void __launch_bounds__(256, 3)
fused_kernel(const float* __restrict__ x, const float* __restrict__ W,
             float* __restrict__ out)
{
    extern __shared__ float smem[];
    float* Abuf = smem;                    // [2][KC][APITCH]
    float* Wt   = smem + NBUF * ABUF;      // [512][20] (+16f guard at end)

    const int tid  = threadIdx.x;
    const int bid  = blockIdx.x;
    const int nt   = bid >> 1;             // image 0..127
    const int half = bid & 1;
    const int off  = half * 96;
    const int nsp  = half ? 100 : 96;
    const int ntiles = half ? 7 : 6;

    const int w  = tid >> 5;
    const int l  = tid & 31;
    const int lg = l >> 2;
    const int lc = l & 3;

    // ======================= PHASE 1: logits + softmax =======================
    for (int i = tid; i < OO * CCH; i += 256) {
        const int n = i >> 9, k = i & (CCH - 1);
        Wt[k * WTP + n] = W[i];
    }

    const float* xbase = x + (size_t)nt * CCH * HWS + off;
    const uint32_t abase_u32 = smem_u32(Abuf);

    auto stage = [&](int ck) {
        const float* src = xbase + (size_t)ck * KC * HWS;
        const uint32_t dst0 = abase_u32 + (ck & (NBUF - 1)) * (ABUF * 4);
        if (half == 0) {
            for (int f = tid; f < KC * 24; f += 256) {
                const int c = f / 24, i = f - c * 24;
                CP16(dst0 + (c * APITCH + 4 * i) * 4, src + c * HWS + 4 * i);
            }
        } else {
            for (int f = tid; f < KC * 25; f += 256) {
                const int c = f / 25, i = f - c * 25;
                CP16(dst0 + (c * APITCH + 4 * i) * 4, src + c * HWS + 4 * i);
            }
        }
        asm volatile("cp.async.commit_group;" ::: "memory");
    };

    const bool tvalid = (w < ntiles);
    const int sp0 = 16 * w + lg;
    const int spa = min(sp0, APITCH - 1);
    const int spb = min(sp0 + 8, APITCH - 1);

    float d[3][4];
#pragma unroll
    for (int nf = 0; nf < 3; ++nf)
#pragma unroll
        for (int r = 0; r < 4; ++r) d[nf][r] = 0.f;

    stage(0); stage(1);

    for (int ck = 0; ck < NCHUNK; ++ck) {
        if (ck < NCHUNK - 1) {
            asm volatile("cp.async.wait_group 1;" ::: "memory");
        } else {
            asm volatile("cp.async.wait_group 0;" ::: "memory");
        }
        __syncthreads();

        const float* Ab = Abuf + (ck & (NBUF - 1)) * ABUF;
#pragma unroll
        for (int k8 = 0; k8 < KC / 8; ++k8) {
            const int kl = k8 * 8;
            const int kg = ck * KC + kl + lc;
            uint32_t bfr[3][2];
#pragma unroll
            for (int nf = 0; nf < 3; ++nf) {
                bfr[nf][0] = __float_as_uint(Wt[kg * WTP + 8 * nf + lg]);
                bfr[nf][1] = __float_as_uint(Wt[(kg + 4) * WTP + 8 * nf + lg]);
            }
            if (tvalid) {
                const float* r0 = Ab + (kl + lc) * APITCH;
                const float* r4 = Ab + (kl + lc + 4) * APITCH;
                const uint32_t a0 = __float_as_uint(r0[spa]);
                const uint32_t a1 = __float_as_uint(r0[spb]);
                const uint32_t a2 = __float_as_uint(r4[spa]);
                const uint32_t a3 = __float_as_uint(r4[spb]);
#pragma unroll
                for (int nf = 0; nf < 3; ++nf)
                    MMA_TF32(d[nf], a0, a1, a2, a3, bfr[nf][0], bfr[nf][1]);
            }
        }
        __syncthreads();
        if (ck + 2 < NCHUNK) stage(ck + 2);
    }

    // exchange D through smem: Dx[112][24]
    float* Dx = smem;
    if (tvalid) {
        const int r = 16 * w + lg;
#pragma unroll
        for (int nf = 0; nf < 3; ++nf) {
            const int col = nf * 8 + 2 * lc;
            Dx[r * 24 + col]           = d[nf][0];
            Dx[r * 24 + col + 1]       = d[nf][1];
            Dx[(r + 8) * 24 + col]     = d[nf][2];
            Dx[(r + 8) * 24 + col + 1] = d[nf][3];
        }
    }
    __syncthreads();

    const int t_  = nt & (TT - 1);
    const int n_i = nt >> 3;
    for (int s = tid; s < nsp; s += 256) {
        const float* row = Dx + s * 24;
        const int b = n_i * HWS + off + s;
#pragma unroll
        for (int h = 0; h < HH; ++h) {
            float lo[KK];
#pragma unroll
            for (int k = 0; k < KK; ++k) lo[k] = row[h * KK + k];
            float m = lo[0];
#pragma unroll
            for (int k = 1; k < KK; ++k) m = fmaxf(m, lo[k]);
            float e[KK], sum = 0.f;
#pragma unroll
            for (int k = 0; k < KK; ++k) { e[k] = __expf(lo[k] - m); sum += e[k]; }
            const float inv = 1.f / sum;
#pragma unroll
            for (int k = 0; k < KK; ++k)
                g_weights[GW_IDX(h, t_, k, b)] = e[k] * inv;
        }
    }

    // ================== group sync: 16 CTAs per segment ======================
    __threadfence();                      // publish weights (all threads)
    __syncthreads();
    const int grp = bid >> 4;             // == n_i
    if (tid == 0) {
        atomicAdd(&g_arrive[grp], 1u);
        while (atomicAdd(&g_arrive[grp], 0u) < 16u) { }
    }
    __syncthreads();                      // whole block sees group complete

    // ======================= PHASE 2: causal combine =========================
    // this CTA: segment grp, 32-channel tile c0 = (bid&15)*32, head = c0/128
    {
        const int c0 = (bid & 15) * 32;
        const int h2 = c0 >> 7;
        const int sp = tid;
        if (sp < HWS) {
            const int b = grp * HWS + sp;
            float wt[TT * KK];
#pragma unroll
            for (int t = 0; t < TT; ++t)
#pragma unroll
                for (int k = 0; k < KK; ++k)
                    wt[t * KK + k] = g_weights[GW_IDX(h2, t, k, b)];

            const size_t tstride = (size_t)CCH * HWS;
            const size_t base = ((size_t)grp * TT * CCH + (size_t)c0) * HWS + sp;

#pragma unroll 2
            for (int cp = 0; cp < 16; ++cp) {
                const float* xp0 = x + base + (size_t)(2 * cp) * HWS;
                const float* xp1 = xp0 + HWS;
                float a[TT], bv[TT];
#pragma unroll
                for (int t = 0; t < TT; ++t) a[t]  = xp0[(size_t)t * tstride];
#pragma unroll
                for (int t = 0; t < TT; ++t) bv[t] = xp1[(size_t)t * tstride];

                float* op0 = out + base + (size_t)(2 * cp) * HWS;
                float* op1 = op0 + HWS;
#pragma unroll
                for (int t = 0; t < TT; ++t) {
                    float s0 = 0.f, s1 = 0.f;
#pragma unroll
                    for (int k = 0; k < KK; ++k) {
                        const int src = t + k - 4;
                        if (src >= 0) {
                            s0 = fmaf(wt[t * KK + k], a[src],  s0);
                            s1 = fmaf(wt[t * KK + k], bv[src], s1);
                        }
                    }
                    op0[(size_t)t * tstride] = s0;
                    op1[(size_t)t * tstride] = s1;
                }
            }
        }
    }

    // ================== counter reset (graph-replay safe) ====================
    __syncthreads();
    if (tid == 0) {
        if (atomicAdd(&g_done[grp], 1u) == 15u) {
            atomicExch(&g_arrive[grp], 0u);
            atomicExch(&g_done[grp], 0u);
        }
    }
}

// ---------------------------------------------------------------------------
extern "C" void kernel_launch(void* const* d_in, const int* in_sizes, int n_in,
                              void* d_out, int out_size)
{
    const float* x = (const float*)d_in[0];
    const float* W = (const float*)d_in[1];
    float* out = (float*)d_out;

    cudaFuncSetAttribute(fused_kernel,
                         cudaFuncAttributeMaxDynamicSharedMemorySize, SMEM1_BYTES);

    fused_kernel<<<2 * NT, 256, SMEM1_BYTES>>>(x, W, out);
}